// round 1
// baseline (speedup 1.0000x reference)
#include <cuda_runtime.h>
#include <cuda_bf16.h>
#include <cstdint>

// Problem constants
#define BB 16
#define SS 4096
#define DD 1024
#define MM 512

// ---------------------------------------------------------------------------
// Scratch (device globals; no allocations allowed)
// ---------------------------------------------------------------------------
__device__ float g_q[(size_t)BB * SS * MM];   // q = x Wq^T + bq
__device__ float g_k[(size_t)BB * SS * MM];   // ak = a*(x Wk^T + bk)   (alpha folded)
__device__ float g_v[(size_t)BB * SS * MM];   // v = x Wv^T + bv

// ---------------------------------------------------------------------------
// Packed f32x2 helpers (Blackwell FFMA2 path: 2x fp32 FMA throughput)
// ---------------------------------------------------------------------------
__device__ __forceinline__ float2 ffma2(float2 a, float2 b, float2 c) {
    unsigned long long ua = *(unsigned long long*)&a;
    unsigned long long ub = *(unsigned long long*)&b;
    unsigned long long uc = *(unsigned long long*)&c;
    unsigned long long ud;
    asm("fma.rn.f32x2 %0, %1, %2, %3;" : "=l"(ud) : "l"(ua), "l"(ub), "l"(uc));
    return *(float2*)&ud;
}

__device__ __forceinline__ float2 fmul2(float2 a, float2 b) {
    unsigned long long ua = *(unsigned long long*)&a;
    unsigned long long ub = *(unsigned long long*)&b;
    unsigned long long ud;
    asm("mul.rn.f32x2 %0, %1, %2;" : "=l"(ud) : "l"(ua), "l"(ub));
    return *(float2*)&ud;
}

// ---------------------------------------------------------------------------
// GEMM: C[n, m] = scale * (sum_d X[n, d] * W[m, d] + bias[m])
// X: (65536, 1024) row-major. W: (512, 1024) row-major (both K-major -> NT GEMM).
// Tile 128x128, BK=16, 256 threads, 8x8 per thread, f32x2 inner FMAs.
// which: 0 -> g_q (scale 1), 1 -> g_k (scale a), 2 -> g_v (scale 1)
// ---------------------------------------------------------------------------
__global__ __launch_bounds__(256, 2)
void qkv_gemm_kernel(const float* __restrict__ X,
                     const float* __restrict__ W,
                     const float* __restrict__ bias,
                     const float* __restrict__ alpha_p,
                     int which)
{
    constexpr int BK = 16;

    __shared__ float As[BK][128];
    __shared__ float Bs[BK][128];

    const int tid = threadIdx.x;
    const int tx = tid & 15;       // column group (8 cols)
    const int ty = tid >> 4;       // row group (8 rows)

    const int c0 = blockIdx.x * 128;   // output column base (M dim)
    const int r0 = blockIdx.y * 128;   // output row base (B*S dim)

    const int rA = tid >> 2;           // 0..63
    const int cA = (tid & 3) * 4;      // 0,4,8,12

    float* outp = (which == 0) ? g_q : (which == 1) ? g_k : g_v;

    float2 c[8][4];
    #pragma unroll
    for (int i = 0; i < 8; i++)
        #pragma unroll
        for (int j = 0; j < 4; j++) c[i][j] = make_float2(0.f, 0.f);

    // prefetch registers
    float4 pa0, pa1, pb0, pb1;

    const float* Xa0 = X + (size_t)(r0 + rA) * DD + cA;
    const float* Xa1 = X + (size_t)(r0 + rA + 64) * DD + cA;
    const float* Wb0 = W + (size_t)(c0 + rA) * DD + cA;
    const float* Wb1 = W + (size_t)(c0 + rA + 64) * DD + cA;

    // prefetch ktile 0
    pa0 = *(const float4*)(Xa0);
    pa1 = *(const float4*)(Xa1);
    pb0 = *(const float4*)(Wb0);
    pb1 = *(const float4*)(Wb1);

    for (int kt = 0; kt < DD / BK; ++kt) {
        __syncthreads();
        // store staged tile
        As[cA + 0][rA] = pa0.x; As[cA + 1][rA] = pa0.y;
        As[cA + 2][rA] = pa0.z; As[cA + 3][rA] = pa0.w;
        As[cA + 0][rA + 64] = pa1.x; As[cA + 1][rA + 64] = pa1.y;
        As[cA + 2][rA + 64] = pa1.z; As[cA + 3][rA + 64] = pa1.w;
        Bs[cA + 0][rA] = pb0.x; Bs[cA + 1][rA] = pb0.y;
        Bs[cA + 2][rA] = pb0.z; Bs[cA + 3][rA] = pb0.w;
        Bs[cA + 0][rA + 64] = pb1.x; Bs[cA + 1][rA + 64] = pb1.y;
        Bs[cA + 2][rA + 64] = pb1.z; Bs[cA + 3][rA + 64] = pb1.w;
        __syncthreads();

        // prefetch next ktile while computing this one
        if (kt + 1 < DD / BK) {
            int off = (kt + 1) * BK;
            pa0 = *(const float4*)(Xa0 + off);
            pa1 = *(const float4*)(Xa1 + off);
            pb0 = *(const float4*)(Wb0 + off);
            pb1 = *(const float4*)(Wb1 + off);
        }

        #pragma unroll
        for (int kk = 0; kk < BK; ++kk) {
            float4 a0 = *(const float4*)&As[kk][ty * 8];
            float4 a1 = *(const float4*)&As[kk][ty * 8 + 4];
            float4 b0 = *(const float4*)&Bs[kk][tx * 8];
            float4 b1 = *(const float4*)&Bs[kk][tx * 8 + 4];
            float av[8] = {a0.x, a0.y, a0.z, a0.w, a1.x, a1.y, a1.z, a1.w};
            float2 bv2[4] = {{b0.x, b0.y}, {b0.z, b0.w}, {b1.x, b1.y}, {b1.z, b1.w}};
            #pragma unroll
            for (int i = 0; i < 8; i++) {
                float2 ad = make_float2(av[i], av[i]);
                #pragma unroll
                for (int j = 0; j < 4; j++)
                    c[i][j] = ffma2(ad, bv2[j], c[i][j]);
            }
        }
    }

    // epilogue: + bias, optional *a scale (fold alpha into k projection)
    float scale = 1.0f;
    if (which == 1) {
        float al = alpha_p[0];
        scale = 1.0f / (1.0f + expf(-al));
    }
    const int col = c0 + tx * 8;
    float bsv[8];
    #pragma unroll
    for (int j = 0; j < 8; j++) bsv[j] = bias[col + j];

    const int row0 = r0 + ty * 8;
    #pragma unroll
    for (int i = 0; i < 8; i++) {
        float4 o0, o1;
        o0.x = scale * (c[i][0].x + bsv[0]);
        o0.y = scale * (c[i][0].y + bsv[1]);
        o0.z = scale * (c[i][1].x + bsv[2]);
        o0.w = scale * (c[i][1].y + bsv[3]);
        o1.x = scale * (c[i][2].x + bsv[4]);
        o1.y = scale * (c[i][2].y + bsv[5]);
        o1.z = scale * (c[i][3].x + bsv[6]);
        o1.w = scale * (c[i][3].y + bsv[7]);
        *(float4*)&outp[(size_t)(row0 + i) * MM + col] = o0;
        *(float4*)&outp[(size_t)(row0 + i) * MM + col + 4] = o1;
    }
}

// ---------------------------------------------------------------------------
// Scan: per block = (batch b, 32-column slice of Mem). Mem slice lives in
// registers: 8 warps x 4 cols/warp; lane l holds rows {i*32 + l}, i=0..15.
// Per step: r_n = sum_m q_m Mem[m,n]  (old Mem), then
//           Mem = (1-a) Mem + (a k)_m v_n   (a pre-folded into g_k).
// q/ak/v staged through double-buffered SMEM, one __syncthreads per step.
// ---------------------------------------------------------------------------
__global__ __launch_bounds__(256, 2)
void scan_kernel(const float* __restrict__ alpha_p,
                 float* __restrict__ out,
                 long long out_elems)
{
    const int cs = blockIdx.x;   // column slice 0..15
    const int b  = blockIdx.y;   // batch 0..15
    const int tid = threadIdx.x;
    const int w = tid >> 5;      // warp 0..7
    const int l = tid & 31;      // lane

    const float al = alpha_p[0];
    const float a = 1.0f / (1.0f + expf(-al));
    const float oma = 1.0f - a;
    const float2 oma2 = make_float2(oma, oma);

    __shared__ float sq[2][MM];
    __shared__ float sk[2][MM];
    __shared__ float sv[2][32];

    const float* qb = g_q + (size_t)b * SS * MM;
    const float* kb = g_k + (size_t)b * SS * MM;
    const float* vb = g_v + (size_t)b * SS * MM + cs * 32;

    // Mem state in registers: mem[i][p] = Mem[i*32 + l][cs*32 + w*4 + 2p .. +2p+1]
    float2 mem[16][2];
    #pragma unroll
    for (int i = 0; i < 16; i++) {
        mem[i][0] = make_float2(0.f, 0.f);
        mem[i][1] = make_float2(0.f, 0.f);
    }

    // stage t=0 into buffer 0
    {
        if (tid < 128)
            *(float4*)&sq[0][tid * 4] = *(const float4*)&qb[tid * 4];
        else
            *(float4*)&sk[0][(tid - 128) * 4] = *(const float4*)&kb[(tid - 128) * 4];
        if (tid < 8)
            *(float4*)&sv[0][tid * 4] = *(const float4*)&vb[tid * 4];
    }

    const int nloc = w * 4;                    // local column base within slice
    const int nglob = cs * 32 + nloc;          // global column base
    float* outb = out + ((size_t)b * SS) * MM + nglob;

    for (int t = 0; t < SS; ++t) {
        __syncthreads();
        const int buf = t & 1;

        // stage next step into the other buffer
        if (t + 1 < SS) {
            const size_t off = (size_t)(t + 1) * MM;
            if (tid < 128)
                *(float4*)&sq[buf ^ 1][tid * 4] = *(const float4*)&qb[off + tid * 4];
            else
                *(float4*)&sk[buf ^ 1][(tid - 128) * 4] = *(const float4*)&kb[off + (tid - 128) * 4];
            if (tid < 8)
                *(float4*)&sv[buf ^ 1][tid * 4] = *(const float4*)&vb[off + tid * 4];
        }

        // compute current step
        float2 v0 = *(float2*)&sv[buf][nloc];
        float2 v1 = *(float2*)&sv[buf][nloc + 2];
        float2 r0 = make_float2(0.f, 0.f);
        float2 r1 = make_float2(0.f, 0.f);

        #pragma unroll
        for (int i = 0; i < 16; i++) {
            const int m = i * 32 + l;
            float qi = sq[buf][m];
            float ki = sk[buf][m];
            float2 q2 = make_float2(qi, qi);
            float2 k2 = make_float2(ki, ki);
            // read (old Mem) before write
            r0 = ffma2(q2, mem[i][0], r0);
            r1 = ffma2(q2, mem[i][1], r1);
            mem[i][0] = ffma2(oma2, mem[i][0], fmul2(k2, v0));
            mem[i][1] = ffma2(oma2, mem[i][1], fmul2(k2, v1));
        }

        // reduce r over the 32 lanes (rows)
        #pragma unroll
        for (int off = 16; off; off >>= 1) {
            r0.x += __shfl_xor_sync(0xFFFFFFFFu, r0.x, off);
            r0.y += __shfl_xor_sync(0xFFFFFFFFu, r0.y, off);
            r1.x += __shfl_xor_sync(0xFFFFFFFFu, r1.x, off);
            r1.y += __shfl_xor_sync(0xFFFFFFFFu, r1.y, off);
        }

        if (l == 0) {
            float4 o = make_float4(r0.x, r0.y, r1.x, r1.y);
            *(float4*)&outb[(size_t)t * MM] = o;
        }
    }

    // Final memory state Mf -> second output (if the harness buffer holds it)
    const long long mf_base = (long long)BB * SS * MM;
    if (out_elems >= mf_base + (long long)BB * MM * MM) {
        float* mf = out + mf_base + (size_t)b * MM * MM;
        #pragma unroll
        for (int i = 0; i < 16; i++) {
            const int m = i * 32 + l;
            float4 val = make_float4(mem[i][0].x, mem[i][0].y, mem[i][1].x, mem[i][1].y);
            *(float4*)&mf[(size_t)m * MM + nglob] = val;
        }
    }
}

// ---------------------------------------------------------------------------
// Launch
// ---------------------------------------------------------------------------
extern "C" void kernel_launch(void* const* d_in, const int* in_sizes, int n_in,
                              void* d_out, int out_size)
{
    const float* x     = (const float*)d_in[0];
    const float* Wq    = (const float*)d_in[1];
    const float* bq    = (const float*)d_in[2];
    const float* Wk    = (const float*)d_in[3];
    const float* bk    = (const float*)d_in[4];
    const float* Wv    = (const float*)d_in[5];
    const float* bv    = (const float*)d_in[6];
    const float* alpha = (const float*)d_in[7];
    float* out = (float*)d_out;

    dim3 gg(MM / 128, (BB * SS) / 128);   // (4, 512)
    qkv_gemm_kernel<<<gg, 256>>>(x, Wq, bq, alpha, 0);
    qkv_gemm_kernel<<<gg, 256>>>(x, Wk, bk, alpha, 1);
    qkv_gemm_kernel<<<gg, 256>>>(x, Wv, bv, alpha, 2);

    dim3 gs(16, 16);                       // (col-slice, batch)
    scan_kernel<<<gs, 256>>>(alpha, out, (long long)out_size);
}

// round 2
// speedup vs baseline: 1.0050x; 1.0050x over previous
#include <cuda_runtime.h>
#include <cuda_bf16.h>
#include <cstdint>

// Problem constants
#define BB 16
#define SS 4096
#define DD 1024
#define MM 512

// ---------------------------------------------------------------------------
// Scratch (device globals; no allocations allowed)
// ---------------------------------------------------------------------------
__device__ float g_q[(size_t)BB * SS * MM];   // q = x Wq^T + bq
__device__ float g_k[(size_t)BB * SS * MM];   // ak = a*(x Wk^T + bk)   (alpha folded)
__device__ float g_v[(size_t)BB * SS * MM];   // v = x Wv^T + bv

// ---------------------------------------------------------------------------
// Packed f32x2 helpers (Blackwell FFMA2 path: 2x fp32 FMA throughput)
// ---------------------------------------------------------------------------
__device__ __forceinline__ float2 ffma2(float2 a, float2 b, float2 c) {
    unsigned long long ua = *(unsigned long long*)&a;
    unsigned long long ub = *(unsigned long long*)&b;
    unsigned long long uc = *(unsigned long long*)&c;
    unsigned long long ud;
    asm("fma.rn.f32x2 %0, %1, %2, %3;" : "=l"(ud) : "l"(ua), "l"(ub), "l"(uc));
    return *(float2*)&ud;
}

__device__ __forceinline__ float2 fmul2(float2 a, float2 b) {
    unsigned long long ua = *(unsigned long long*)&a;
    unsigned long long ub = *(unsigned long long*)&b;
    unsigned long long ud;
    asm("mul.rn.f32x2 %0, %1, %2;" : "=l"(ud) : "l"(ua), "l"(ub));
    return *(float2*)&ud;
}

// ---------------------------------------------------------------------------
// GEMM: C[n, m] = scale * (sum_d X[n, d] * W[m, d] + bias[m])
// X: (65536, 1024) row-major. W: (512, 1024) row-major (both K-major -> NT GEMM).
// Tile 128x128, BK=16, 256 threads, 8x8 per thread, f32x2 inner FMAs.
// which: 0 -> g_q (scale 1), 1 -> g_k (scale a), 2 -> g_v (scale 1)
// ---------------------------------------------------------------------------
__global__ __launch_bounds__(256, 2)
void qkv_gemm_kernel(const float* __restrict__ X,
                     const float* __restrict__ W,
                     const float* __restrict__ bias,
                     const float* __restrict__ alpha_p,
                     int which)
{
    constexpr int BK = 16;

    __shared__ float As[BK][128];
    __shared__ float Bs[BK][128];

    const int tid = threadIdx.x;
    const int tx = tid & 15;       // column group (8 cols)
    const int ty = tid >> 4;       // row group (8 rows)

    const int c0 = blockIdx.x * 128;   // output column base (M dim)
    const int r0 = blockIdx.y * 128;   // output row base (B*S dim)

    const int rA = tid >> 2;           // 0..63
    const int cA = (tid & 3) * 4;      // 0,4,8,12

    float* outp = (which == 0) ? g_q : (which == 1) ? g_k : g_v;

    float2 c[8][4];
    #pragma unroll
    for (int i = 0; i < 8; i++)
        #pragma unroll
        for (int j = 0; j < 4; j++) c[i][j] = make_float2(0.f, 0.f);

    // prefetch registers
    float4 pa0, pa1, pb0, pb1;

    const float* Xa0 = X + (size_t)(r0 + rA) * DD + cA;
    const float* Xa1 = X + (size_t)(r0 + rA + 64) * DD + cA;
    const float* Wb0 = W + (size_t)(c0 + rA) * DD + cA;
    const float* Wb1 = W + (size_t)(c0 + rA + 64) * DD + cA;

    // prefetch ktile 0
    pa0 = *(const float4*)(Xa0);
    pa1 = *(const float4*)(Xa1);
    pb0 = *(const float4*)(Wb0);
    pb1 = *(const float4*)(Wb1);

    for (int kt = 0; kt < DD / BK; ++kt) {
        __syncthreads();
        // store staged tile
        As[cA + 0][rA] = pa0.x; As[cA + 1][rA] = pa0.y;
        As[cA + 2][rA] = pa0.z; As[cA + 3][rA] = pa0.w;
        As[cA + 0][rA + 64] = pa1.x; As[cA + 1][rA + 64] = pa1.y;
        As[cA + 2][rA + 64] = pa1.z; As[cA + 3][rA + 64] = pa1.w;
        Bs[cA + 0][rA] = pb0.x; Bs[cA + 1][rA] = pb0.y;
        Bs[cA + 2][rA] = pb0.z; Bs[cA + 3][rA] = pb0.w;
        Bs[cA + 0][rA + 64] = pb1.x; Bs[cA + 1][rA + 64] = pb1.y;
        Bs[cA + 2][rA + 64] = pb1.z; Bs[cA + 3][rA + 64] = pb1.w;
        __syncthreads();

        // prefetch next ktile while computing this one
        if (kt + 1 < DD / BK) {
            int off = (kt + 1) * BK;
            pa0 = *(const float4*)(Xa0 + off);
            pa1 = *(const float4*)(Xa1 + off);
            pb0 = *(const float4*)(Wb0 + off);
            pb1 = *(const float4*)(Wb1 + off);
        }

        #pragma unroll
        for (int kk = 0; kk < BK; ++kk) {
            float4 a0 = *(const float4*)&As[kk][ty * 8];
            float4 a1 = *(const float4*)&As[kk][ty * 8 + 4];
            float4 b0 = *(const float4*)&Bs[kk][tx * 8];
            float4 b1 = *(const float4*)&Bs[kk][tx * 8 + 4];
            float av[8] = {a0.x, a0.y, a0.z, a0.w, a1.x, a1.y, a1.z, a1.w};
            float2 bv2[4] = {{b0.x, b0.y}, {b0.z, b0.w}, {b1.x, b1.y}, {b1.z, b1.w}};
            #pragma unroll
            for (int i = 0; i < 8; i++) {
                float2 ad = make_float2(av[i], av[i]);
                #pragma unroll
                for (int j = 0; j < 4; j++)
                    c[i][j] = ffma2(ad, bv2[j], c[i][j]);
            }
        }
    }

    // epilogue: + bias, optional *a scale (fold alpha into k projection)
    float scale = 1.0f;
    if (which == 1) {
        float al = alpha_p[0];
        scale = 1.0f / (1.0f + expf(-al));
    }
    const int col = c0 + tx * 8;
    float bsv[8];
    #pragma unroll
    for (int j = 0; j < 8; j++) bsv[j] = bias[col + j];

    const int row0 = r0 + ty * 8;
    #pragma unroll
    for (int i = 0; i < 8; i++) {
        float4 o0, o1;
        o0.x = scale * (c[i][0].x + bsv[0]);
        o0.y = scale * (c[i][0].y + bsv[1]);
        o0.z = scale * (c[i][1].x + bsv[2]);
        o0.w = scale * (c[i][1].y + bsv[3]);
        o1.x = scale * (c[i][2].x + bsv[4]);
        o1.y = scale * (c[i][2].y + bsv[5]);
        o1.z = scale * (c[i][3].x + bsv[6]);
        o1.w = scale * (c[i][3].y + bsv[7]);
        *(float4*)&outp[(size_t)(row0 + i) * MM + col] = o0;
        *(float4*)&outp[(size_t)(row0 + i) * MM + col + 4] = o1;
    }
}

// ---------------------------------------------------------------------------
// Scan: per block = (batch b, 32-column slice of Mem). Mem slice lives in
// registers: 8 warps x 4 cols/warp; lane l holds rows {i*32 + l}, i=0..15.
// Per step: r_n = sum_m q_m Mem[m,n]  (old Mem), then
//           Mem = (1-a) Mem + (a k)_m v_n   (a pre-folded into g_k).
// q/ak/v staged through double-buffered SMEM, one __syncthreads per step.
// ---------------------------------------------------------------------------
__global__ __launch_bounds__(256, 2)
void scan_kernel(const float* __restrict__ alpha_p,
                 float* __restrict__ out,
                 long long out_elems)
{
    const int cs = blockIdx.x;   // column slice 0..15
    const int b  = blockIdx.y;   // batch 0..15
    const int tid = threadIdx.x;
    const int w = tid >> 5;      // warp 0..7
    const int l = tid & 31;      // lane

    const float al = alpha_p[0];
    const float a = 1.0f / (1.0f + expf(-al));
    const float oma = 1.0f - a;
    const float2 oma2 = make_float2(oma, oma);

    __shared__ float sq[2][MM];
    __shared__ float sk[2][MM];
    __shared__ float sv[2][32];

    const float* qb = g_q + (size_t)b * SS * MM;
    const float* kb = g_k + (size_t)b * SS * MM;
    const float* vb = g_v + (size_t)b * SS * MM + cs * 32;

    // Mem state in registers: mem[i][p] = Mem[i*32 + l][cs*32 + w*4 + 2p .. +2p+1]
    float2 mem[16][2];
    #pragma unroll
    for (int i = 0; i < 16; i++) {
        mem[i][0] = make_float2(0.f, 0.f);
        mem[i][1] = make_float2(0.f, 0.f);
    }

    // stage t=0 into buffer 0
    {
        if (tid < 128)
            *(float4*)&sq[0][tid * 4] = *(const float4*)&qb[tid * 4];
        else
            *(float4*)&sk[0][(tid - 128) * 4] = *(const float4*)&kb[(tid - 128) * 4];
        if (tid < 8)
            *(float4*)&sv[0][tid * 4] = *(const float4*)&vb[tid * 4];
    }

    const int nloc = w * 4;                    // local column base within slice
    const int nglob = cs * 32 + nloc;          // global column base
    float* outb = out + ((size_t)b * SS) * MM + nglob;

    for (int t = 0; t < SS; ++t) {
        __syncthreads();
        const int buf = t & 1;

        // stage next step into the other buffer
        if (t + 1 < SS) {
            const size_t off = (size_t)(t + 1) * MM;
            if (tid < 128)
                *(float4*)&sq[buf ^ 1][tid * 4] = *(const float4*)&qb[off + tid * 4];
            else
                *(float4*)&sk[buf ^ 1][(tid - 128) * 4] = *(const float4*)&kb[off + (tid - 128) * 4];
            if (tid < 8)
                *(float4*)&sv[buf ^ 1][tid * 4] = *(const float4*)&vb[off + tid * 4];
        }

        // compute current step
        float2 v0 = *(float2*)&sv[buf][nloc];
        float2 v1 = *(float2*)&sv[buf][nloc + 2];
        float2 r0 = make_float2(0.f, 0.f);
        float2 r1 = make_float2(0.f, 0.f);

        #pragma unroll
        for (int i = 0; i < 16; i++) {
            const int m = i * 32 + l;
            float qi = sq[buf][m];
            float ki = sk[buf][m];
            float2 q2 = make_float2(qi, qi);
            float2 k2 = make_float2(ki, ki);
            // read (old Mem) before write
            r0 = ffma2(q2, mem[i][0], r0);
            r1 = ffma2(q2, mem[i][1], r1);
            mem[i][0] = ffma2(oma2, mem[i][0], fmul2(k2, v0));
            mem[i][1] = ffma2(oma2, mem[i][1], fmul2(k2, v1));
        }

        // reduce r over the 32 lanes (rows)
        #pragma unroll
        for (int off = 16; off; off >>= 1) {
            r0.x += __shfl_xor_sync(0xFFFFFFFFu, r0.x, off);
            r0.y += __shfl_xor_sync(0xFFFFFFFFu, r0.y, off);
            r1.x += __shfl_xor_sync(0xFFFFFFFFu, r1.x, off);
            r1.y += __shfl_xor_sync(0xFFFFFFFFu, r1.y, off);
        }

        if (l == 0) {
            float4 o = make_float4(r0.x, r0.y, r1.x, r1.y);
            *(float4*)&outb[(size_t)t * MM] = o;
        }
    }

    // Final memory state Mf -> second output (if the harness buffer holds it)
    const long long mf_base = (long long)BB * SS * MM;
    if (out_elems >= mf_base + (long long)BB * MM * MM) {
        float* mf = out + mf_base + (size_t)b * MM * MM;
        #pragma unroll
        for (int i = 0; i < 16; i++) {
            const int m = i * 32 + l;
            float4 val = make_float4(mem[i][0].x, mem[i][0].y, mem[i][1].x, mem[i][1].y);
            *(float4*)&mf[(size_t)m * MM + nglob] = val;
        }
    }
}

// ---------------------------------------------------------------------------
// Launch
// ---------------------------------------------------------------------------
extern "C" void kernel_launch(void* const* d_in, const int* in_sizes, int n_in,
                              void* d_out, int out_size)
{
    const float* x     = (const float*)d_in[0];
    const float* Wq    = (const float*)d_in[1];
    const float* bq    = (const float*)d_in[2];
    const float* Wk    = (const float*)d_in[3];
    const float* bk    = (const float*)d_in[4];
    const float* Wv    = (const float*)d_in[5];
    const float* bv    = (const float*)d_in[6];
    const float* alpha = (const float*)d_in[7];
    float* out = (float*)d_out;

    dim3 gg(MM / 128, (BB * SS) / 128);   // (4, 512)
    qkv_gemm_kernel<<<gg, 256>>>(x, Wq, bq, alpha, 0);
    qkv_gemm_kernel<<<gg, 256>>>(x, Wk, bk, alpha, 1);
    qkv_gemm_kernel<<<gg, 256>>>(x, Wv, bv, alpha, 2);

    dim3 gs(16, 16);                       // (col-slice, batch)
    scan_kernel<<<gs, 256>>>(alpha, out, (long long)out_size);
}

// round 10
// speedup vs baseline: 1.5062x; 1.4988x over previous
#include <cuda_runtime.h>
#include <cuda_bf16.h>
#include <cstdint>

#define BB 16
#define SS 4096
#define DD 1024
#define MM 512

// ---------------- scratch (device globals; no allocs allowed) ----------------
__device__ float g_q[(size_t)BB * SS * MM];
__device__ float g_k[(size_t)BB * SS * MM];   // a*(xWk+bk), alpha folded
__device__ float g_v[(size_t)BB * SS * MM];
__device__ __align__(16) __nv_bfloat16 g_xhi[(size_t)BB * SS * DD];
__device__ __align__(16) __nv_bfloat16 g_xlo[(size_t)BB * SS * DD];
__device__ __align__(16) __nv_bfloat16 g_whi[(size_t)3 * MM * DD];
__device__ __align__(16) __nv_bfloat16 g_wlo[(size_t)3 * MM * DD];

// ---------------- f32x2 helpers (scan) ----------------
__device__ __forceinline__ float2 ffma2(float2 a, float2 b, float2 c) {
    unsigned long long ua=*(unsigned long long*)&a, ub=*(unsigned long long*)&b,
                       uc=*(unsigned long long*)&c, ud;
    asm("fma.rn.f32x2 %0, %1, %2, %3;" : "=l"(ud) : "l"(ua), "l"(ub), "l"(uc));
    return *(float2*)&ud;
}
__device__ __forceinline__ float2 fmul2(float2 a, float2 b) {
    unsigned long long ua=*(unsigned long long*)&a, ub=*(unsigned long long*)&b, ud;
    asm("mul.rn.f32x2 %0, %1, %2;" : "=l"(ud) : "l"(ua), "l"(ub));
    return *(float2*)&ud;
}

// ---------------- PTX helpers (sm_80-era only: safe on compute_103) --------
__device__ __forceinline__ uint32_t smem_u32(const void* p) {
    uint32_t r;
    asm("{ .reg .u64 t; cvta.to.shared.u64 t, %1; cvt.u32.u64 %0, t; }" : "=r"(r) : "l"(p));
    return r;
}
__device__ __forceinline__ void cp16(uint32_t s, const void* g) {
    asm volatile("cp.async.cg.shared.global [%0], [%1], 16;" :: "r"(s), "l"(g));
}
#define CP_COMMIT() asm volatile("cp.async.commit_group;" ::: "memory")
#define CP_WAIT0()  asm volatile("cp.async.wait_group 0;" ::: "memory")
#define CP_WAIT1()  asm volatile("cp.async.wait_group 1;" ::: "memory")

#define LDSM4(r, addr) \
    asm volatile("ldmatrix.sync.aligned.m8n8.x4.shared.b16 {%0,%1,%2,%3}, [%4];" \
        : "=r"((r)[0]), "=r"((r)[1]), "=r"((r)[2]), "=r"((r)[3]) : "r"(addr))

#define MMA16816(c, a, b0, b1) \
    asm volatile("mma.sync.aligned.m16n8k16.row.col.f32.bf16.bf16.f32 " \
        "{%0,%1,%2,%3}, {%4,%5,%6,%7}, {%8,%9}, {%0,%1,%2,%3};" \
        : "+f"((c)[0]), "+f"((c)[1]), "+f"((c)[2]), "+f"((c)[3]) \
        : "r"((a)[0]), "r"((a)[1]), "r"((a)[2]), "r"((a)[3]), "r"(b0), "r"(b1))

// ---------------- bf16 hi/lo split pre-passes ----------------
__global__ __launch_bounds__(256)
void cvt_x_kernel(const float* __restrict__ x) {
    size_t i = ((size_t)blockIdx.x * 256 + threadIdx.x) * 8;
    float4 a = *(const float4*)(x + i);
    float4 b = *(const float4*)(x + i + 4);
    float v[8] = {a.x,a.y,a.z,a.w,b.x,b.y,b.z,b.w};
    __align__(16) __nv_bfloat16 h[8], l[8];
    #pragma unroll
    for (int j = 0; j < 8; j++) {
        h[j] = __float2bfloat16_rn(v[j]);
        l[j] = __float2bfloat16_rn(v[j] - __bfloat162float(h[j]));
    }
    *(uint4*)(g_xhi + i) = *(uint4*)h;
    *(uint4*)(g_xlo + i) = *(uint4*)l;
}
__global__ __launch_bounds__(256)
void cvt_w_kernel(const float* __restrict__ Wq, const float* __restrict__ Wk,
                  const float* __restrict__ Wv) {
    size_t i = ((size_t)blockIdx.x * 256 + threadIdx.x) * 8;
    int mtx = (int)(i >> 19);            // 512*1024 per matrix
    size_t off = i & 524287;
    const float* src = (mtx == 0) ? Wq : (mtx == 1) ? Wk : Wv;
    float4 a = *(const float4*)(src + off);
    float4 b = *(const float4*)(src + off + 4);
    float v[8] = {a.x,a.y,a.z,a.w,b.x,b.y,b.z,b.w};
    __align__(16) __nv_bfloat16 h[8], l[8];
    #pragma unroll
    for (int j = 0; j < 8; j++) {
        h[j] = __float2bfloat16_rn(v[j]);
        l[j] = __float2bfloat16_rn(v[j] - __bfloat162float(h[j]));
    }
    *(uint4*)(g_whi + i) = *(uint4*)h;
    *(uint4*)(g_wlo + i) = *(uint4*)l;
}

// ---------------- mma.sync GEMM ----------------
// CTA: 128x128 tile of out[r,n] = scale*(sum_d X[r,d] W[n,d] + bias[n]).
// 3xBF16: acc = Xhi*Whi + Xhi*Wlo + Xlo*Whi in fp32 regs. BK=32, 2-stage cp.async.
// smem per stage: 4 matrices (Ah, Al, Bh, Bl), each 128 rows x 32 bf16, padded
// row stride 80B (conflict-free ldmatrix: banks 20r mod 32 all distinct).
#define ROWB 80
#define MAT  10240          // 128 * 80
#define STG  40960          // 4 * MAT
#define GEMM_SMEM 81920     // 2 stages

__device__ __forceinline__ void ldchunk(uint32_t s, uint32_t so1, uint32_t so2,
    const __nv_bfloat16* gAh, const __nv_bfloat16* gAl,
    const __nv_bfloat16* gBh, const __nv_bfloat16* gBl, int ko, size_t g2)
{
    cp16(s + so1,           gAh + ko);      cp16(s + so2,           gAh + ko + g2);
    cp16(s + MAT + so1,     gAl + ko);      cp16(s + MAT + so2,     gAl + ko + g2);
    cp16(s + 2*MAT + so1,   gBh + ko);      cp16(s + 2*MAT + so2,   gBh + ko + g2);
    cp16(s + 3*MAT + so1,   gBl + ko);      cp16(s + 3*MAT + so2,   gBl + ko + g2);
    CP_COMMIT();
}

__global__ __launch_bounds__(256, 2)
void mma_gemm_kernel(const float* __restrict__ bq, const float* __restrict__ bk,
                     const float* __restrict__ bv, const float* __restrict__ alpha_p)
{
    extern __shared__ char smem[];
    const uint32_t sb = smem_u32(smem);
    const int tid = threadIdx.x;
    const int lane = tid & 31, wid = tid >> 5;
    const int wm = wid >> 1, wn = wid & 1;          // 4x2 warp grid; warp tile 32x64
    const int mtx = blockIdx.x >> 2;
    const int n0  = (blockIdx.x & 3) * 128;
    const int r0  = blockIdx.y * 128;

    // cp.async thread mapping: 128 rows x 4 x 16B units per matrix
    const int lr = tid >> 2;            // 0..63
    const int lc = tid & 3;             // 0..3
    const uint32_t so1 = lr * ROWB + lc * 16;
    const uint32_t so2 = so1 + 64 * ROWB;
    const size_t g2 = (size_t)64 * DD;

    const __nv_bfloat16* gAh = g_xhi + (size_t)(r0 + lr) * DD + lc * 8;
    const __nv_bfloat16* gAl = g_xlo + (size_t)(r0 + lr) * DD + lc * 8;
    const __nv_bfloat16* gBh = g_whi + ((size_t)mtx * MM + n0 + lr) * DD + lc * 8;
    const __nv_bfloat16* gBl = g_wlo + ((size_t)mtx * MM + n0 + lr) * DD + lc * 8;

    // ldmatrix fragment base offsets (bytes)
    const uint32_t aoff = (uint32_t)(wm * 32 + (lane & 15)) * ROWB + (lane >> 4) * 16;
    const uint32_t boff = (uint32_t)(wn * 64 + ((lane >> 4) & 1) * 8 + (lane & 7)) * ROWB
                        + ((lane >> 3) & 1) * 16;

    float c[2][8][4];
    #pragma unroll
    for (int i = 0; i < 2; i++)
        #pragma unroll
        for (int j = 0; j < 8; j++)
            #pragma unroll
            for (int t = 0; t < 4; t++) c[i][j][t] = 0.f;

    ldchunk(sb, so1, so2, gAh, gAl, gBh, gBl, 0, g2);

    #pragma unroll 1
    for (int ch = 0; ch < 32; ++ch) {
        if (ch + 1 < 32) {
            ldchunk(sb + ((ch + 1) & 1) * STG, so1, so2, gAh, gAl, gBh, gBl,
                    (ch + 1) * 32, g2);
            CP_WAIT1();
        } else {
            CP_WAIT0();
        }
        __syncthreads();

        const uint32_t st = sb + (ch & 1) * STG;
        #pragma unroll
        for (int ks = 0; ks < 2; ++ks) {
            #pragma unroll
            for (int ps = 0; ps < 3; ++ps) {
                // passes: (Ah,Bh), (Ah,Bl), (Al,Bh)
                const uint32_t Abase = st + ((ps == 2) ? MAT : 0);
                const uint32_t Bbase = st + ((ps == 1) ? 3 * MAT : 2 * MAT);
                uint32_t a[2][4], b[4][4];
                LDSM4(a[0], Abase + aoff + ks * 32);
                LDSM4(a[1], Abase + aoff + 16 * ROWB + ks * 32);
                #pragma unroll
                for (int p = 0; p < 4; p++)
                    LDSM4(b[p], Bbase + boff + p * 16 * ROWB + ks * 32);
                #pragma unroll
                for (int mt = 0; mt < 2; mt++)
                    #pragma unroll
                    for (int p = 0; p < 4; p++) {
                        MMA16816(c[mt][2*p],   a[mt], b[p][0], b[p][1]);
                        MMA16816(c[mt][2*p+1], a[mt], b[p][2], b[p][3]);
                    }
            }
        }
        __syncthreads();
    }

    // epilogue: bias + optional sigmoid(alpha) scale
    float scale = 1.0f;
    if (mtx == 1) scale = 1.0f / (1.0f + expf(-alpha_p[0]));
    const float* bias = (mtx == 0) ? bq : (mtx == 1) ? bk : bv;
    float* outp = (mtx == 0) ? g_q : (mtx == 1) ? g_k : g_v;

    const int mrow = r0 + wm * 32 + (lane >> 2);
    const int nc0  = n0 + wn * 64 + (lane & 3) * 2;
    #pragma unroll
    for (int mt = 0; mt < 2; mt++) {
        const int m = mrow + mt * 16;
        #pragma unroll
        for (int nt = 0; nt < 8; nt++) {
            const int n = nc0 + nt * 8;
            const float b0v = bias[n], b1v = bias[n + 1];
            float2 o0 = make_float2(scale * (c[mt][nt][0] + b0v),
                                    scale * (c[mt][nt][1] + b1v));
            float2 o1 = make_float2(scale * (c[mt][nt][2] + b0v),
                                    scale * (c[mt][nt][3] + b1v));
            *(float2*)&outp[(size_t)m * MM + n]       = o0;
            *(float2*)&outp[(size_t)(m + 8) * MM + n] = o1;
        }
    }
}

// ---------------- scan (unchanged from passing R0 kernel) ----------------
__global__ __launch_bounds__(256, 2)
void scan_kernel(const float* __restrict__ alpha_p, float* __restrict__ out,
                 long long out_elems)
{
    const int cs = blockIdx.x, b = blockIdx.y;
    const int tid = threadIdx.x, w = tid >> 5, l = tid & 31;
    const float a = 1.0f / (1.0f + expf(-alpha_p[0]));
    const float2 oma2 = make_float2(1.0f - a, 1.0f - a);

    __shared__ float sq[2][MM];
    __shared__ float sk[2][MM];
    __shared__ float sv[2][32];

    const float* qb = g_q + (size_t)b * SS * MM;
    const float* kb = g_k + (size_t)b * SS * MM;
    const float* vb = g_v + (size_t)b * SS * MM + cs * 32;

    float2 mem[16][2];
    #pragma unroll
    for (int i = 0; i < 16; i++) { mem[i][0] = make_float2(0.f,0.f); mem[i][1] = make_float2(0.f,0.f); }

    if (tid < 128) *(float4*)&sq[0][tid*4] = *(const float4*)&qb[tid*4];
    else           *(float4*)&sk[0][(tid-128)*4] = *(const float4*)&kb[(tid-128)*4];
    if (tid < 8)   *(float4*)&sv[0][tid*4] = *(const float4*)&vb[tid*4];

    const int nloc = w * 4;
    const int nglob = cs * 32 + nloc;
    float* outb = out + (size_t)b * SS * MM + nglob;

    for (int t = 0; t < SS; ++t) {
        __syncthreads();
        const int buf = t & 1;
        if (t + 1 < SS) {
            const size_t off = (size_t)(t + 1) * MM;
            if (tid < 128) *(float4*)&sq[buf^1][tid*4] = *(const float4*)&qb[off + tid*4];
            else           *(float4*)&sk[buf^1][(tid-128)*4] = *(const float4*)&kb[off + (tid-128)*4];
            if (tid < 8)   *(float4*)&sv[buf^1][tid*4] = *(const float4*)&vb[off + tid*4];
        }
        float2 v0 = *(float2*)&sv[buf][nloc];
        float2 v1 = *(float2*)&sv[buf][nloc + 2];
        float2 r0 = make_float2(0.f,0.f), r1 = make_float2(0.f,0.f);
        #pragma unroll
        for (int i = 0; i < 16; i++) {
            const int m = i * 32 + l;
            float qi = sq[buf][m], ki = sk[buf][m];
            float2 q2 = make_float2(qi,qi), k2 = make_float2(ki,ki);
            r0 = ffma2(q2, mem[i][0], r0);
            r1 = ffma2(q2, mem[i][1], r1);
            mem[i][0] = ffma2(oma2, mem[i][0], fmul2(k2, v0));
            mem[i][1] = ffma2(oma2, mem[i][1], fmul2(k2, v1));
        }
        #pragma unroll
        for (int off = 16; off; off >>= 1) {
            r0.x += __shfl_xor_sync(0xFFFFFFFFu, r0.x, off);
            r0.y += __shfl_xor_sync(0xFFFFFFFFu, r0.y, off);
            r1.x += __shfl_xor_sync(0xFFFFFFFFu, r1.x, off);
            r1.y += __shfl_xor_sync(0xFFFFFFFFu, r1.y, off);
        }
        if (l == 0) *(float4*)&outb[(size_t)t * MM] = make_float4(r0.x, r0.y, r1.x, r1.y);
    }

    const long long mf_base = (long long)BB * SS * MM;
    if (out_elems >= mf_base + (long long)BB * MM * MM) {
        float* mf = out + mf_base + (size_t)b * MM * MM;
        #pragma unroll
        for (int i = 0; i < 16; i++) {
            const int m = i * 32 + l;
            *(float4*)&mf[(size_t)m * MM + nglob] =
                make_float4(mem[i][0].x, mem[i][0].y, mem[i][1].x, mem[i][1].y);
        }
    }
}

// ---------------- launch ----------------
extern "C" void kernel_launch(void* const* d_in, const int* in_sizes, int n_in,
                              void* d_out, int out_size)
{
    const float* x     = (const float*)d_in[0];
    const float* Wq    = (const float*)d_in[1];
    const float* bq    = (const float*)d_in[2];
    const float* Wk    = (const float*)d_in[3];
    const float* bk    = (const float*)d_in[4];
    const float* Wv    = (const float*)d_in[5];
    const float* bv    = (const float*)d_in[6];
    const float* alpha = (const float*)d_in[7];
    float* out = (float*)d_out;

    cudaFuncSetAttribute(mma_gemm_kernel, cudaFuncAttributeMaxDynamicSharedMemorySize, GEMM_SMEM);

    cvt_x_kernel<<<(BB * SS * DD) / (256 * 8), 256>>>(x);
    cvt_w_kernel<<<(3 * MM * DD) / (256 * 8), 256>>>(Wq, Wk, Wv);

    dim3 gg(12, 512);   // x: mtx*4 + ntile (fast) -> A reuse in L2; y: rowblock
    mma_gemm_kernel<<<gg, 256, GEMM_SMEM>>>(bq, bk, bv, alpha);

    dim3 gs(16, 16);
    scan_kernel<<<gs, 256>>>(alpha, out, (long long)out_size);
}